// round 2
// baseline (speedup 1.0000x reference)
#include <cuda_runtime.h>
#include <math.h>

#define BATCH 16384
#define DIN   512
#define HDIM  256

// -------- scratch (static device allocations; no cudaMalloc allowed) --------
__device__ float g_spec[8 * BATCH * HDIM];     // [z = n*2+e][b][h]   134 MB
__device__ float g_shared[4 * BATCH * HDIM];   // [e][b][h]            67 MB
__device__ float g_glog[4 * BATCH * 6];        // domain gate logits
__device__ float g_gslog[BATCH * 12];          // shared gate logits

// ============================================================================
// GEMM: out[z] = relu(A @ W + bias), A = (16384 x 512), W = (512 x 256)
// z < 8 : spec (A = xd[z/2], W = W_spec[z]) ; z >= 8 : shared (A = xs, W = W_sh)
// Tiling: BM=128, BN=128, BK=16, 256 threads, 8x8 per thread (split 4+4).
// ============================================================================
__global__ __launch_bounds__(256, 2)
void gemm_bias_relu(const float* __restrict__ x,
                    const float* __restrict__ Wspec, const float* __restrict__ bspec,
                    const float* __restrict__ Wsh,   const float* __restrict__ bsh)
{
    __shared__ float As[16][132];   // [k][m], padded (stride 132: odd-ish bank mix)
    __shared__ float Bs[16][128];   // [k][n]

    const int z = blockIdx.z;
    const float* A; const float* W; const float* bias; float* out;
    if (z < 8) {
        A    = x + (size_t)(z >> 1) * BATCH * DIN;
        W    = Wspec + (size_t)z * DIN * HDIM;
        bias = bspec + z * HDIM;
        out  = g_spec + (size_t)z * BATCH * HDIM;
    } else {
        A    = x + (size_t)4 * BATCH * DIN;
        W    = Wsh + (size_t)(z - 8) * DIN * HDIM;
        bias = bsh + (z - 8) * HDIM;
        out  = g_shared + (size_t)(z - 8) * BATCH * HDIM;
    }

    const int tid = threadIdx.x;
    const int tx  = tid & 15;   // 0..15 -> n fragment
    const int ty  = tid >> 4;   // 0..15 -> m fragment
    const int m0  = blockIdx.y * 128;
    const int n0  = blockIdx.x * 128;

    // global->smem load mapping
    const int a_m = tid >> 1;          // 0..127
    const int a_k = (tid & 1) << 3;    // 0 or 8
    const int b_n = (tid & 31) << 2;   // 0..124
    const int b_k = tid >> 5;          // 0..7 (and +8)

    const float* Ap = A + (size_t)(m0 + a_m) * DIN + a_k;
    const float* Wp = W + (size_t)b_k * HDIM + n0 + b_n;

    float4 ar0 = *(const float4*)Ap;
    float4 ar1 = *(const float4*)(Ap + 4);
    float4 wr0 = *(const float4*)Wp;
    float4 wr1 = *(const float4*)(Wp + 8 * HDIM);

    float acc[8][8];
#pragma unroll
    for (int i = 0; i < 8; i++)
#pragma unroll
        for (int j = 0; j < 8; j++) acc[i][j] = 0.f;

    const int NT = DIN / 16;   // 32 K-tiles
    for (int kt = 0; kt < NT; ++kt) {
        As[a_k + 0][a_m] = ar0.x; As[a_k + 1][a_m] = ar0.y;
        As[a_k + 2][a_m] = ar0.z; As[a_k + 3][a_m] = ar0.w;
        As[a_k + 4][a_m] = ar1.x; As[a_k + 5][a_m] = ar1.y;
        As[a_k + 6][a_m] = ar1.z; As[a_k + 7][a_m] = ar1.w;
        *(float4*)&Bs[b_k][b_n]     = wr0;
        *(float4*)&Bs[b_k + 8][b_n] = wr1;
        __syncthreads();

        if (kt + 1 < NT) {   // prefetch next tile while computing this one
            Ap += 16; Wp += 16 * HDIM;
            ar0 = *(const float4*)Ap;
            ar1 = *(const float4*)(Ap + 4);
            wr0 = *(const float4*)Wp;
            wr1 = *(const float4*)(Wp + 8 * HDIM);
        }

#pragma unroll
        for (int k = 0; k < 16; ++k) {
            float4 af0 = *(const float4*)&As[k][ty * 4];
            float4 af1 = *(const float4*)&As[k][64 + ty * 4];
            float4 bf0 = *(const float4*)&Bs[k][tx * 4];
            float4 bf1 = *(const float4*)&Bs[k][64 + tx * 4];
            float a[8]  = {af0.x, af0.y, af0.z, af0.w, af1.x, af1.y, af1.z, af1.w};
            float bb[8] = {bf0.x, bf0.y, bf0.z, bf0.w, bf1.x, bf1.y, bf1.z, bf1.w};
#pragma unroll
            for (int i = 0; i < 8; i++)
#pragma unroll
                for (int j = 0; j < 8; j++)
                    acc[i][j] = fmaf(a[i], bb[j], acc[i][j]);
        }
        __syncthreads();
    }

    // epilogue: bias + relu + store
    const float4 bv0 = *(const float4*)&bias[n0 + tx * 4];
    const float4 bv1 = *(const float4*)&bias[n0 + 64 + tx * 4];
#pragma unroll
    for (int gi = 0; gi < 2; ++gi) {
#pragma unroll
        for (int i = 0; i < 4; ++i) {
            const int ii = gi * 4 + i;
            const int row = m0 + gi * 64 + ty * 4 + i;
            float* orow = out + (size_t)row * HDIM + n0;
            float4 v0, v1;
            v0.x = fmaxf(acc[ii][0] + bv0.x, 0.f);
            v0.y = fmaxf(acc[ii][1] + bv0.y, 0.f);
            v0.z = fmaxf(acc[ii][2] + bv0.z, 0.f);
            v0.w = fmaxf(acc[ii][3] + bv0.w, 0.f);
            v1.x = fmaxf(acc[ii][4] + bv1.x, 0.f);
            v1.y = fmaxf(acc[ii][5] + bv1.y, 0.f);
            v1.z = fmaxf(acc[ii][6] + bv1.z, 0.f);
            v1.w = fmaxf(acc[ii][7] + bv1.w, 0.f);
            *(float4*)&orow[tx * 4]      = v0;
            *(float4*)&orow[64 + tx * 4] = v1;
        }
    }
}

// ============================================================================
// Gate logits: one warp per batch row. Domain gates (4 x 6) + shared gate (12).
// ============================================================================
__global__ __launch_bounds__(256)
void gates_kernel(const float* __restrict__ x,
                  const float* __restrict__ Wg,  const float* __restrict__ bg,
                  const float* __restrict__ Wgs, const float* __restrict__ bgs)
{
    const int gwarp = (blockIdx.x * blockDim.x + threadIdx.x) >> 5;
    const int lane  = threadIdx.x & 31;
    if (gwarp >= BATCH) return;
    const int b = gwarp;

#pragma unroll
    for (int n = 0; n < 4; ++n) {
        const float* xr = x + ((size_t)n * BATCH + b) * DIN;
        float xv[16];
#pragma unroll
        for (int i = 0; i < 16; ++i) xv[i] = xr[lane + 32 * i];
#pragma unroll
        for (int e = 0; e < 6; ++e) {
            float acc = 0.f;
#pragma unroll
            for (int i = 0; i < 16; ++i)
                acc = fmaf(xv[i], Wg[(size_t)n * DIN * 6 + (size_t)(lane + 32 * i) * 6 + e], acc);
#pragma unroll
            for (int o = 16; o; o >>= 1) acc += __shfl_xor_sync(0xffffffffu, acc, o);
            if (lane == 0) g_glog[((size_t)n * BATCH + b) * 6 + e] = acc + bg[n * 6 + e];
        }
    }
    {
        const float* xr = x + ((size_t)4 * BATCH + b) * DIN;
        float xv[16];
#pragma unroll
        for (int i = 0; i < 16; ++i) xv[i] = xr[lane + 32 * i];
#pragma unroll
        for (int e = 0; e < 12; ++e) {
            float acc = 0.f;
#pragma unroll
            for (int i = 0; i < 16; ++i)
                acc = fmaf(xv[i], Wgs[(size_t)(lane + 32 * i) * 12 + e], acc);
#pragma unroll
            for (int o = 16; o; o >>= 1) acc += __shfl_xor_sync(0xffffffffu, acc, o);
            if (lane == 0) g_gslog[(size_t)b * 12 + e] = acc + bgs[e];
        }
    }
}

// ============================================================================
// Combine: per row b, per h. Double softmax (softmax, then masked softmax of
// the softmax output — matches reference exactly), then weighted sums.
// ============================================================================
__global__ __launch_bounds__(256)
void combine_kernel(const int* __restrict__ sim, float* __restrict__ out)
{
    const int b = blockIdx.x;
    const int h = threadIdx.x;

    float sp[8];
#pragma unroll
    for (int j = 0; j < 8; ++j)
        sp[j] = g_spec[((size_t)j * BATCH + b) * HDIM + h];
    float sh[4];
#pragma unroll
    for (int e = 0; e < 4; ++e)
        sh[e] = g_shared[((size_t)e * BATCH + b) * HDIM + h];

    // shared gate softmax (12-way)
    float gs[12];
    {
        float m = -1e30f;
#pragma unroll
        for (int j = 0; j < 12; ++j) { gs[j] = g_gslog[(size_t)b * 12 + j]; m = fmaxf(m, gs[j]); }
        float s = 0.f;
#pragma unroll
        for (int j = 0; j < 12; ++j) { gs[j] = __expf(gs[j] - m); s += gs[j]; }
        const float inv = 1.f / s;
        float osh = 0.f;
#pragma unroll
        for (int j = 0; j < 8; ++j)  osh = fmaf(gs[j] * inv, sp[j], osh);
#pragma unroll
        for (int e = 0; e < 4; ++e)  osh = fmaf(gs[8 + e] * inv, sh[e], osh);
        out[((size_t)4 * BATCH + b) * HDIM + h] = osh;
    }

    // per-domain gates: softmax -> mask -> softmax
#pragma unroll
    for (int n = 0; n < 4; ++n) {
        float zz[6];
#pragma unroll
        for (int e = 0; e < 6; ++e) zz[e] = g_glog[((size_t)n * BATCH + b) * 6 + e];
        float m1 = zz[0];
#pragma unroll
        for (int e = 1; e < 6; ++e) m1 = fmaxf(m1, zz[e]);
        float s1 = 0.f;
#pragma unroll
        for (int e = 0; e < 6; ++e) { zz[e] = __expf(zz[e] - m1); s1 += zz[e]; }
        const float inv1 = 1.f / s1;
#pragma unroll
        for (int e = 0; e < 6; ++e) zz[e] *= inv1;

        const int s0 = sim[n * 2], s1i = sim[n * 2 + 1];
        bool valid[6];
        valid[0] = true; valid[1] = true;
#pragma unroll
        for (int e = 0; e < 4; ++e) valid[2 + e] = (s0 == e) || (s1i == e);

        float m2 = -1e30f;
#pragma unroll
        for (int e = 0; e < 6; ++e) if (valid[e]) m2 = fmaxf(m2, zz[e]);
        float w[6]; float s2 = 0.f;
#pragma unroll
        for (int e = 0; e < 6; ++e) { w[e] = valid[e] ? __expf(zz[e] - m2) : 0.f; s2 += w[e]; }
        const float inv2 = 1.f / s2;

        float v = w[0] * sp[n * 2] + w[1] * sp[n * 2 + 1]
                + w[2] * sh[0] + w[3] * sh[1] + w[4] * sh[2] + w[5] * sh[3];
        out[((size_t)n * BATCH + b) * HDIM + h] = v * inv2;
    }
}

// ============================================================================
extern "C" void kernel_launch(void* const* d_in, const int* in_sizes, int n_in,
                              void* d_out, int out_size)
{
    const float* x     = (const float*)d_in[0];   // x_list (5, B, 512)
    const int*   sim   = (const int*)d_in[1];     // sim_domain (4, 2)
    const float* Wspec = (const float*)d_in[2];   // (4, 2, 512, 256)
    const float* bspec = (const float*)d_in[3];   // (4, 2, 256)
    const float* Wsh   = (const float*)d_in[4];   // (4, 512, 256)
    const float* bsh   = (const float*)d_in[5];   // (4, 256)
    const float* Wg    = (const float*)d_in[6];   // (4, 512, 6)
    const float* bg    = (const float*)d_in[7];   // (4, 6)
    const float* Wgs   = (const float*)d_in[8];   // (512, 12)
    const float* bgs   = (const float*)d_in[9];   // (12,)
    float* out = (float*)d_out;                   // (5, B, 256) fp32

    dim3 gemm_grid(HDIM / 128, BATCH / 128, 12);  // (2, 128, 12)
    gemm_bias_relu<<<gemm_grid, 256>>>(x, Wspec, bspec, Wsh, bsh);

    gates_kernel<<<BATCH / 8, 256>>>(x, Wg, bg, Wgs, bgs);

    combine_kernel<<<BATCH, 256>>>(sim, out);
}

// round 4
// speedup vs baseline: 1.6025x; 1.6025x over previous
#include <cuda_runtime.h>
#include <cuda_bf16.h>
#include <math.h>
#include <stdint.h>

#define BATCH 16384
#define DIN   512
#define HDIM  256

// -------- scratch (static device allocations; no cudaMalloc allowed) --------
__device__ float g_spec[8 * BATCH * HDIM];            // [z][b][h]
__device__ float g_shared[4 * BATCH * HDIM];          // [e][b][h]
__device__ float g_glog[4 * BATCH * 6];
__device__ float g_gslog[BATCH * 12];
__device__ __nv_bfloat16 g_xhi[5 * BATCH * DIN];      // bf16 hi of x_list
__device__ __nv_bfloat16 g_xlo[5 * BATCH * DIN];      // bf16 lo residual
__device__ __nv_bfloat16 g_whi[12 * DIN * HDIM];      // [z][k][n] (Wspec 0-7, Wsh 8-11)
__device__ __nv_bfloat16 g_wlo[12 * DIN * HDIM];

// ============================================================================
// helpers (family-common PTX only: cp.async / ldmatrix / mma.sync)
// ============================================================================
__device__ __forceinline__ uint32_t smem_u32(const void* p) {
    uint32_t a;
    asm("{ .reg .u64 t; cvta.to.shared.u64 t, %1; cvt.u32.u64 %0, t; }" : "=r"(a) : "l"(p));
    return a;
}
__device__ __forceinline__ void cpasync16(uint32_t dst, const void* src) {
    asm volatile("cp.async.cg.shared.global [%0], [%1], 16;" :: "r"(dst), "l"(src) : "memory");
}
#define CP_COMMIT() asm volatile("cp.async.commit_group;" ::: "memory")
#define CP_WAIT2()  asm volatile("cp.async.wait_group 2;" ::: "memory")

__device__ __forceinline__ void ldsm4(uint32_t& r0, uint32_t& r1, uint32_t& r2, uint32_t& r3, uint32_t addr) {
    asm volatile("ldmatrix.sync.aligned.m8n8.x4.shared.b16 {%0,%1,%2,%3}, [%4];"
                 : "=r"(r0), "=r"(r1), "=r"(r2), "=r"(r3) : "r"(addr));
}
__device__ __forceinline__ void ldsm4t(uint32_t& r0, uint32_t& r1, uint32_t& r2, uint32_t& r3, uint32_t addr) {
    asm volatile("ldmatrix.sync.aligned.m8n8.x4.trans.shared.b16 {%0,%1,%2,%3}, [%4];"
                 : "=r"(r0), "=r"(r1), "=r"(r2), "=r"(r3) : "r"(addr));
}
__device__ __forceinline__ void mma16816(float* d, const uint32_t* a, uint32_t b0, uint32_t b1) {
    asm volatile(
        "mma.sync.aligned.m16n8k16.row.col.f32.bf16.bf16.f32 "
        "{%0,%1,%2,%3}, {%4,%5,%6,%7}, {%8,%9}, {%0,%1,%2,%3};"
        : "+f"(d[0]), "+f"(d[1]), "+f"(d[2]), "+f"(d[3])
        : "r"(a[0]), "r"(a[1]), "r"(a[2]), "r"(a[3]), "r"(b0), "r"(b1));
}

__device__ __forceinline__ void split2(float a0, float a1, uint32_t& hi, uint32_t& lo) {
    __nv_bfloat16 h0 = __float2bfloat16(a0);
    __nv_bfloat16 h1 = __float2bfloat16(a1);
    __nv_bfloat16 l0 = __float2bfloat16(a0 - __bfloat162float(h0));
    __nv_bfloat16 l1 = __float2bfloat16(a1 - __bfloat162float(h1));
    hi = ((uint32_t)__bfloat16_as_ushort(h1) << 16) | __bfloat16_as_ushort(h0);
    lo = ((uint32_t)__bfloat16_as_ushort(l1) << 16) | __bfloat16_as_ushort(l0);
}

// ============================================================================
// Split kernel: f32 -> (bf16 hi, bf16 lo) for x and all 12 weight matrices.
// ============================================================================
#define NX4  (5 * BATCH * DIN / 4)       // 10,485,760 float4s
#define NWS4 (8 * DIN * HDIM / 4)        // 262,144
#define NWH4 (4 * DIN * HDIM / 4)        // 131,072
#define NSPLIT_BLOCKS ((NX4 + NWS4 + NWH4) / 256)   // 42,496

__global__ __launch_bounds__(256)
void split_kernel(const float4* __restrict__ x,
                  const float4* __restrict__ Ws,
                  const float4* __restrict__ Wh)
{
    const size_t i = (size_t)blockIdx.x * 256 + threadIdx.x;
    float4 v; uint2* dh; uint2* dl; size_t off;
    if (i < NX4) {
        off = i;  v = x[off];
        dh = (uint2*)g_xhi; dl = (uint2*)g_xlo;
    } else {
        off = i - NX4;
        v = (off < NWS4) ? Ws[off] : Wh[off - NWS4];
        dh = (uint2*)g_whi; dl = (uint2*)g_wlo;
    }
    uint32_t h01, l01, h23, l23;
    split2(v.x, v.y, h01, l01);
    split2(v.z, v.w, h23, l23);
    dh[off] = make_uint2(h01, h23);
    dl[off] = make_uint2(l01, l23);
}

// ============================================================================
// Tensor-core GEMM via mma.sync bf16 (3-product split).
// CTA tile 128m x 128n, BK=32, 16 chunks, 4-stage cp.async pipeline.
// 8 warps: warp_m = wid%4 (32 rows), warp_n = wid/4 (64 cols).
// grid = (2 ntiles, 128 mtiles, 12 z), x fastest -> W L2-hot, A reuse.
// ============================================================================
#define OFF_AHI 0
#define OFF_ALO 10240
#define OFF_BHI 20480
#define OFF_BLO 28672
#define STG     36864
#define GEMM_SMEM (4 * STG)   // 147456

__device__ __forceinline__ void issue_chunk(
    uint32_t sm32, int stage, int c0,
    const __nv_bfloat16* __restrict__ xhi, const __nv_bfloat16* __restrict__ xlo,
    const __nv_bfloat16* __restrict__ whi, const __nv_bfloat16* __restrict__ wlo,
    int m0, int n0, int tid)
{
    const uint32_t sa = sm32 + stage * STG;
    // A: 128 rows x 32k hi/lo, padded rows (80B)
#pragma unroll
    for (int i = 0; i < 2; ++i) {
        const int idx = tid + i * 256;
        const int m = idx >> 2, u = idx & 3;
        const size_t go = (size_t)(m0 + m) * DIN + c0 + u * 8;
        const uint32_t d = sa + OFF_AHI + m * 80 + u * 16;
        cpasync16(d, xhi + go);
        cpasync16(d + (OFF_ALO - OFF_AHI), xlo + go);
    }
    // B: 32 k-rows x 128n hi/lo, XOR-swizzled 16B units
#pragma unroll
    for (int i = 0; i < 2; ++i) {
        const int idx = tid + i * 256;
        const int k = idx >> 4, u = idx & 15;
        const size_t go = (size_t)(c0 + k) * HDIM + n0 + u * 8;
        const uint32_t phys = (u & 8) | ((u & 7) ^ (k & 7));
        const uint32_t d = sa + OFF_BHI + k * 256 + phys * 16;
        cpasync16(d, whi + go);
        cpasync16(d + (OFF_BLO - OFF_BHI), wlo + go);
    }
}

__global__ void __launch_bounds__(256, 1)
gemm_tc(const float* __restrict__ bspec, const float* __restrict__ bsh)
{
    extern __shared__ char smem[];
    const uint32_t sm32 = smem_u32(smem);
    const int tid  = threadIdx.x;
    const int wid  = tid >> 5;
    const int lane = tid & 31;
    const int wm0  = (wid & 3) * 32;
    const int wn0  = (wid >> 2) * 64;

    const int n0 = blockIdx.x * 128;
    const int m0 = blockIdx.y * 128;
    const int z  = blockIdx.z;

    const int zsel = (z < 8) ? (z >> 1) : 4;
    const __nv_bfloat16* xhi = g_xhi + (size_t)zsel * BATCH * DIN;
    const __nv_bfloat16* xlo = g_xlo + (size_t)zsel * BATCH * DIN;
    const __nv_bfloat16* whi = g_whi + (size_t)z * DIN * HDIM;
    const __nv_bfloat16* wlo = g_wlo + (size_t)z * DIN * HDIM;
    const float* bias = (z < 8) ? (bspec + z * HDIM) : (bsh + (z - 8) * HDIM);
    float* outp = (z < 8) ? (g_spec + (size_t)z * BATCH * HDIM)
                          : (g_shared + (size_t)(z - 8) * BATCH * HDIM);

    float acc[2][8][4];
#pragma unroll
    for (int f = 0; f < 2; ++f)
#pragma unroll
        for (int j = 0; j < 8; ++j)
#pragma unroll
            for (int q = 0; q < 4; ++q) acc[f][j][q] = 0.f;

    // prologue: 3 stages in flight
#pragma unroll
    for (int p = 0; p < 3; ++p) {
        issue_chunk(sm32, p, p * 32, xhi, xlo, whi, wlo, m0, n0, tid);
        CP_COMMIT();
    }

    for (int kt = 0; kt < 16; ++kt) {
        CP_WAIT2();
        __syncthreads();

        if (kt + 3 < 16)
            issue_chunk(sm32, (kt + 3) & 3, (kt + 3) * 32, xhi, xlo, whi, wlo, m0, n0, tid);
        CP_COMMIT();

        const uint32_t sa = sm32 + (kt & 3) * STG;
#pragma unroll
        for (int ksb = 0; ksb < 2; ++ksb) {
            const int kb = ksb * 16;
            uint32_t ah[2][4], al[2][4];
#pragma unroll
            for (int f = 0; f < 2; ++f) {
                const uint32_t aaddr = sa + OFF_AHI
                    + (wm0 + f * 16 + (lane & 15)) * 80
                    + (kb + ((lane >> 4) << 3)) * 2;
                ldsm4(ah[f][0], ah[f][1], ah[f][2], ah[f][3], aaddr);
                ldsm4(al[f][0], al[f][1], al[f][2], al[f][3], aaddr + (OFF_ALO - OFF_AHI));
            }
            const int g = lane >> 3, r = lane & 7;
            const int krow = kb + (g & 1) * 8 + r;
#pragma unroll
            for (int c = 0; c < 4; ++c) {
                const int noff = wn0 + c * 16 + (g >> 1) * 8;
                const uint32_t u = (uint32_t)(noff >> 3);
                const uint32_t phys = (u & 8) | ((u & 7) ^ (uint32_t)(krow & 7));
                const uint32_t baddr = sa + OFF_BHI + krow * 256 + phys * 16;
                uint32_t bh[4], bl[4];
                ldsm4t(bh[0], bh[1], bh[2], bh[3], baddr);
                ldsm4t(bl[0], bl[1], bl[2], bl[3], baddr + (OFF_BLO - OFF_BHI));
#pragma unroll
                for (int f = 0; f < 2; ++f) {
#pragma unroll
                    for (int jj = 0; jj < 2; ++jj) {
                        float* d = acc[f][2 * c + jj];
                        mma16816(d, ah[f], bh[2 * jj], bh[2 * jj + 1]);
                        mma16816(d, ah[f], bl[2 * jj], bl[2 * jj + 1]);
                        mma16816(d, al[f], bh[2 * jj], bh[2 * jj + 1]);
                    }
                }
            }
        }
    }

    // epilogue: bias + relu, direct global stores (float2 per half-frag)
#pragma unroll
    for (int f = 0; f < 2; ++f) {
#pragma unroll
        for (int j = 0; j < 8; ++j) {
            const int row = m0 + wm0 + f * 16 + (lane >> 2);
            const int col = n0 + wn0 + j * 8 + (lane & 3) * 2;
            const float b0 = __ldg(&bias[col]);
            const float b1 = __ldg(&bias[col + 1]);
            float2 v0, v1;
            v0.x = fmaxf(acc[f][j][0] + b0, 0.f);
            v0.y = fmaxf(acc[f][j][1] + b1, 0.f);
            v1.x = fmaxf(acc[f][j][2] + b0, 0.f);
            v1.y = fmaxf(acc[f][j][3] + b1, 0.f);
            *(float2*)(outp + (size_t)row * HDIM + col)       = v0;
            *(float2*)(outp + (size_t)(row + 8) * HDIM + col) = v1;
        }
    }
}

// ============================================================================
// Gate logits: one warp per batch row.
// ============================================================================
__global__ __launch_bounds__(256)
void gates_kernel(const float* __restrict__ x,
                  const float* __restrict__ Wg,  const float* __restrict__ bg,
                  const float* __restrict__ Wgs, const float* __restrict__ bgs)
{
    const int gwarp = (blockIdx.x * blockDim.x + threadIdx.x) >> 5;
    const int lane  = threadIdx.x & 31;
    if (gwarp >= BATCH) return;
    const int b = gwarp;

#pragma unroll
    for (int n = 0; n < 4; ++n) {
        const float* xr = x + ((size_t)n * BATCH + b) * DIN;
        float xv[16];
#pragma unroll
        for (int i = 0; i < 16; ++i) xv[i] = xr[lane + 32 * i];
#pragma unroll
        for (int e = 0; e < 6; ++e) {
            float acc = 0.f;
#pragma unroll
            for (int i = 0; i < 16; ++i)
                acc = fmaf(xv[i], Wg[(size_t)n * DIN * 6 + (size_t)(lane + 32 * i) * 6 + e], acc);
#pragma unroll
            for (int o = 16; o; o >>= 1) acc += __shfl_xor_sync(0xffffffffu, acc, o);
            if (lane == 0) g_glog[((size_t)n * BATCH + b) * 6 + e] = acc + bg[n * 6 + e];
        }
    }
    {
        const float* xr = x + ((size_t)4 * BATCH + b) * DIN;
        float xv[16];
#pragma unroll
        for (int i = 0; i < 16; ++i) xv[i] = xr[lane + 32 * i];
#pragma unroll
        for (int e = 0; e < 12; ++e) {
            float acc = 0.f;
#pragma unroll
            for (int i = 0; i < 16; ++i)
                acc = fmaf(xv[i], Wgs[(size_t)(lane + 32 * i) * 12 + e], acc);
#pragma unroll
            for (int o = 16; o; o >>= 1) acc += __shfl_xor_sync(0xffffffffu, acc, o);
            if (lane == 0) g_gslog[(size_t)b * 12 + e] = acc + bgs[e];
        }
    }
}

// ============================================================================
// Combine: double softmax (matches reference), weighted sums.
// ============================================================================
__global__ __launch_bounds__(256)
void combine_kernel(const int* __restrict__ sim, float* __restrict__ out)
{
    const int b = blockIdx.x;
    const int h = threadIdx.x;

    float sp[8];
#pragma unroll
    for (int j = 0; j < 8; ++j)
        sp[j] = g_spec[((size_t)j * BATCH + b) * HDIM + h];
    float sh[4];
#pragma unroll
    for (int e = 0; e < 4; ++e)
        sh[e] = g_shared[((size_t)e * BATCH + b) * HDIM + h];

    {
        float gs[12];
        float m = -1e30f;
#pragma unroll
        for (int j = 0; j < 12; ++j) { gs[j] = g_gslog[(size_t)b * 12 + j]; m = fmaxf(m, gs[j]); }
        float sum = 0.f;
#pragma unroll
        for (int j = 0; j < 12; ++j) { gs[j] = __expf(gs[j] - m); sum += gs[j]; }
        const float inv = 1.f / sum;
        float osh = 0.f;
#pragma unroll
        for (int j = 0; j < 8; ++j)  osh = fmaf(gs[j] * inv, sp[j], osh);
#pragma unroll
        for (int e = 0; e < 4; ++e)  osh = fmaf(gs[8 + e] * inv, sh[e], osh);
        out[((size_t)4 * BATCH + b) * HDIM + h] = osh;
    }

#pragma unroll
    for (int n = 0; n < 4; ++n) {
        float zz[6];
#pragma unroll
        for (int e = 0; e < 6; ++e) zz[e] = g_glog[((size_t)n * BATCH + b) * 6 + e];
        float m1 = zz[0];
#pragma unroll
        for (int e = 1; e < 6; ++e) m1 = fmaxf(m1, zz[e]);
        float s1 = 0.f;
#pragma unroll
        for (int e = 0; e < 6; ++e) { zz[e] = __expf(zz[e] - m1); s1 += zz[e]; }
        const float inv1 = 1.f / s1;
#pragma unroll
        for (int e = 0; e < 6; ++e) zz[e] *= inv1;

        const int s0 = sim[n * 2], s1i = sim[n * 2 + 1];
        bool valid[6];
        valid[0] = true; valid[1] = true;
#pragma unroll
        for (int e = 0; e < 4; ++e) valid[2 + e] = (s0 == e) || (s1i == e);

        float m2 = -1e30f;
#pragma unroll
        for (int e = 0; e < 6; ++e) if (valid[e]) m2 = fmaxf(m2, zz[e]);
        float w[6]; float s2 = 0.f;
#pragma unroll
        for (int e = 0; e < 6; ++e) { w[e] = valid[e] ? __expf(zz[e] - m2) : 0.f; s2 += w[e]; }
        const float inv2 = 1.f / s2;

        float v = w[0] * sp[n * 2] + w[1] * sp[n * 2 + 1]
                + w[2] * sh[0] + w[3] * sh[1] + w[4] * sh[2] + w[5] * sh[3];
        out[((size_t)n * BATCH + b) * HDIM + h] = v * inv2;
    }
}

// ============================================================================
extern "C" void kernel_launch(void* const* d_in, const int* in_sizes, int n_in,
                              void* d_out, int out_size)
{
    const float* x     = (const float*)d_in[0];
    const int*   sim   = (const int*)d_in[1];
    const float* Wspec = (const float*)d_in[2];
    const float* bspec = (const float*)d_in[3];
    const float* Wsh   = (const float*)d_in[4];
    const float* bsh   = (const float*)d_in[5];
    const float* Wg    = (const float*)d_in[6];
    const float* bg    = (const float*)d_in[7];
    const float* Wgs   = (const float*)d_in[8];
    const float* bgs   = (const float*)d_in[9];
    float* out = (float*)d_out;

    split_kernel<<<NSPLIT_BLOCKS, 256>>>((const float4*)x, (const float4*)Wspec,
                                         (const float4*)Wsh);

    cudaFuncSetAttribute(gemm_tc, cudaFuncAttributeMaxDynamicSharedMemorySize, GEMM_SMEM);
    dim3 gemm_grid(2, 128, 12);
    gemm_tc<<<gemm_grid, 256, GEMM_SMEM>>>(bspec, bsh);

    gates_kernel<<<BATCH / 8, 256>>>(x, Wg, bg, Wgs, bgs);

    combine_kernel<<<BATCH, 256>>>(sim, out);
}

// round 5
// speedup vs baseline: 1.9446x; 1.2135x over previous
#include <cuda_runtime.h>
#include <cuda_bf16.h>
#include <math.h>
#include <stdint.h>

#define BATCH 16384
#define DIN   512
#define HDIM  256

// -------- scratch (static device allocations; no cudaMalloc allowed) --------
__device__ float g_spec[8 * BATCH * HDIM];            // [z][b][h]
__device__ float g_shared[4 * BATCH * HDIM];          // [e][b][h]
__device__ float g_gw[4 * BATCH * 6];                 // FINAL domain gate weights
__device__ float g_gsw[BATCH * 12];                   // FINAL shared gate weights
__device__ __nv_bfloat16 g_xhi[5 * BATCH * DIN];
__device__ __nv_bfloat16 g_xlo[5 * BATCH * DIN];
__device__ __nv_bfloat16 g_whi[12 * DIN * HDIM];      // [z][k][n]
__device__ __nv_bfloat16 g_wlo[12 * DIN * HDIM];

// ============================================================================
// helpers (family-common PTX only: cp.async / ldmatrix / mma.sync)
// ============================================================================
__device__ __forceinline__ uint32_t smem_u32(const void* p) {
    uint32_t a;
    asm("{ .reg .u64 t; cvta.to.shared.u64 t, %1; cvt.u32.u64 %0, t; }" : "=r"(a) : "l"(p));
    return a;
}
__device__ __forceinline__ void cpasync16(uint32_t dst, const void* src) {
    asm volatile("cp.async.cg.shared.global [%0], [%1], 16;" :: "r"(dst), "l"(src) : "memory");
}
#define CP_COMMIT() asm volatile("cp.async.commit_group;" ::: "memory")
#define CP_WAIT1()  asm volatile("cp.async.wait_group 1;" ::: "memory")

__device__ __forceinline__ void ldsm4(uint32_t& r0, uint32_t& r1, uint32_t& r2, uint32_t& r3, uint32_t addr) {
    asm volatile("ldmatrix.sync.aligned.m8n8.x4.shared.b16 {%0,%1,%2,%3}, [%4];"
                 : "=r"(r0), "=r"(r1), "=r"(r2), "=r"(r3) : "r"(addr));
}
__device__ __forceinline__ void ldsm4t(uint32_t& r0, uint32_t& r1, uint32_t& r2, uint32_t& r3, uint32_t addr) {
    asm volatile("ldmatrix.sync.aligned.m8n8.x4.trans.shared.b16 {%0,%1,%2,%3}, [%4];"
                 : "=r"(r0), "=r"(r1), "=r"(r2), "=r"(r3) : "r"(addr));
}
__device__ __forceinline__ void mma16816(float* d, const uint32_t* a, uint32_t b0, uint32_t b1) {
    asm volatile(
        "mma.sync.aligned.m16n8k16.row.col.f32.bf16.bf16.f32 "
        "{%0,%1,%2,%3}, {%4,%5,%6,%7}, {%8,%9}, {%0,%1,%2,%3};"
        : "+f"(d[0]), "+f"(d[1]), "+f"(d[2]), "+f"(d[3])
        : "r"(a[0]), "r"(a[1]), "r"(a[2]), "r"(a[3]), "r"(b0), "r"(b1));
}

__device__ __forceinline__ void split2(float a0, float a1, uint32_t& hi, uint32_t& lo) {
    __nv_bfloat16 h0 = __float2bfloat16(a0);
    __nv_bfloat16 h1 = __float2bfloat16(a1);
    __nv_bfloat16 l0 = __float2bfloat16(a0 - __bfloat162float(h0));
    __nv_bfloat16 l1 = __float2bfloat16(a1 - __bfloat162float(h1));
    hi = ((uint32_t)__bfloat16_as_ushort(h1) << 16) | __bfloat16_as_ushort(h0);
    lo = ((uint32_t)__bfloat16_as_ushort(l1) << 16) | __bfloat16_as_ushort(l0);
}

// ============================================================================
// Split kernel: f32 -> (bf16 hi, bf16 lo) for x and all 12 weight matrices.
// ============================================================================
#define NX4  (5 * BATCH * DIN / 4)
#define NWS4 (8 * DIN * HDIM / 4)
#define NWH4 (4 * DIN * HDIM / 4)
#define NSPLIT_BLOCKS ((NX4 + NWS4 + NWH4) / 256)

__global__ __launch_bounds__(256)
void split_kernel(const float4* __restrict__ x,
                  const float4* __restrict__ Ws,
                  const float4* __restrict__ Wh)
{
    const size_t i = (size_t)blockIdx.x * 256 + threadIdx.x;
    float4 v; uint2* dh; uint2* dl; size_t off;
    if (i < NX4) {
        off = i;  v = x[off];
        dh = (uint2*)g_xhi; dl = (uint2*)g_xlo;
    } else {
        off = i - NX4;
        v = (off < NWS4) ? Ws[off] : Wh[off - NWS4];
        dh = (uint2*)g_whi; dl = (uint2*)g_wlo;
    }
    uint32_t h01, l01, h23, l23;
    split2(v.x, v.y, h01, l01);
    split2(v.z, v.w, h23, l23);
    dh[off] = make_uint2(h01, h23);
    dl[off] = make_uint2(l01, l23);
}

// ============================================================================
// Tensor-core GEMM via mma.sync bf16 (3-product split).
// CTA tile 128m x 128n, BK=32, 16 chunks, 3-stage cp.async pipeline,
// 2 CTAs/SM (108KB smem each).
// ============================================================================
#define OFF_AHI 0
#define OFF_ALO 10240
#define OFF_BHI 20480
#define OFF_BLO 28672
#define STG     36864
#define GEMM_SMEM (3 * STG)   // 110592

__device__ __forceinline__ void issue_chunk(
    uint32_t sm32, int stage, int c0,
    const __nv_bfloat16* __restrict__ xhi, const __nv_bfloat16* __restrict__ xlo,
    const __nv_bfloat16* __restrict__ whi, const __nv_bfloat16* __restrict__ wlo,
    int m0, int n0, int tid)
{
    const uint32_t sa = sm32 + stage * STG;
    // A: 128 rows x 32k hi/lo, padded rows (80B)
#pragma unroll
    for (int i = 0; i < 2; ++i) {
        const int idx = tid + i * 256;
        const int m = idx >> 2, u = idx & 3;
        const size_t go = (size_t)(m0 + m) * DIN + c0 + u * 8;
        const uint32_t d = sa + OFF_AHI + m * 80 + u * 16;
        cpasync16(d, xhi + go);
        cpasync16(d + (OFF_ALO - OFF_AHI), xlo + go);
    }
    // B: 32 k-rows x 128n hi/lo, XOR-swizzled 16B units
#pragma unroll
    for (int i = 0; i < 2; ++i) {
        const int idx = tid + i * 256;
        const int k = idx >> 4, u = idx & 15;
        const size_t go = (size_t)(c0 + k) * HDIM + n0 + u * 8;
        const uint32_t phys = (u & 8) | ((u & 7) ^ (k & 7));
        const uint32_t d = sa + OFF_BHI + k * 256 + phys * 16;
        cpasync16(d, whi + go);
        cpasync16(d + (OFF_BLO - OFF_BHI), wlo + go);
    }
}

__global__ void __launch_bounds__(256, 2)
gemm_tc(const float* __restrict__ bspec, const float* __restrict__ bsh)
{
    extern __shared__ char smem[];
    const uint32_t sm32 = smem_u32(smem);
    const int tid  = threadIdx.x;
    const int wid  = tid >> 5;
    const int lane = tid & 31;
    const int wm0  = (wid & 3) * 32;
    const int wn0  = (wid >> 2) * 64;

    const int n0 = blockIdx.x * 128;
    const int m0 = blockIdx.y * 128;
    const int z  = blockIdx.z;

    const int zsel = (z < 8) ? (z >> 1) : 4;
    const __nv_bfloat16* xhi = g_xhi + (size_t)zsel * BATCH * DIN;
    const __nv_bfloat16* xlo = g_xlo + (size_t)zsel * BATCH * DIN;
    const __nv_bfloat16* whi = g_whi + (size_t)z * DIN * HDIM;
    const __nv_bfloat16* wlo = g_wlo + (size_t)z * DIN * HDIM;
    const float* bias = (z < 8) ? (bspec + z * HDIM) : (bsh + (z - 8) * HDIM);
    float* outp = (z < 8) ? (g_spec + (size_t)z * BATCH * HDIM)
                          : (g_shared + (size_t)(z - 8) * BATCH * HDIM);

    float acc[2][8][4];
#pragma unroll
    for (int f = 0; f < 2; ++f)
#pragma unroll
        for (int j = 0; j < 8; ++j)
#pragma unroll
            for (int q = 0; q < 4; ++q) acc[f][j][q] = 0.f;

    // prologue: 2 stages in flight
#pragma unroll
    for (int p = 0; p < 2; ++p) {
        issue_chunk(sm32, p, p * 32, xhi, xlo, whi, wlo, m0, n0, tid);
        CP_COMMIT();
    }

    for (int kt = 0; kt < 16; ++kt) {
        CP_WAIT1();
        __syncthreads();

        if (kt + 2 < 16)
            issue_chunk(sm32, (kt + 2) % 3, (kt + 2) * 32, xhi, xlo, whi, wlo, m0, n0, tid);
        CP_COMMIT();

        const uint32_t sa = sm32 + (kt % 3) * STG;
#pragma unroll
        for (int ksb = 0; ksb < 2; ++ksb) {
            const int kb = ksb * 16;
            uint32_t ah[2][4], al[2][4];
#pragma unroll
            for (int f = 0; f < 2; ++f) {
                const uint32_t aaddr = sa + OFF_AHI
                    + (wm0 + f * 16 + (lane & 15)) * 80
                    + (kb + ((lane >> 4) << 3)) * 2;
                ldsm4(ah[f][0], ah[f][1], ah[f][2], ah[f][3], aaddr);
                ldsm4(al[f][0], al[f][1], al[f][2], al[f][3], aaddr + (OFF_ALO - OFF_AHI));
            }
            const int g = lane >> 3, r = lane & 7;
            const int krow = kb + (g & 1) * 8 + r;
#pragma unroll
            for (int c = 0; c < 4; ++c) {
                const int noff = wn0 + c * 16 + (g >> 1) * 8;
                const uint32_t u = (uint32_t)(noff >> 3);
                const uint32_t phys = (u & 8) | ((u & 7) ^ (uint32_t)(krow & 7));
                const uint32_t baddr = sa + OFF_BHI + krow * 256 + phys * 16;
                uint32_t bh[4], bl[4];
                ldsm4t(bh[0], bh[1], bh[2], bh[3], baddr);
                ldsm4t(bl[0], bl[1], bl[2], bl[3], baddr + (OFF_BLO - OFF_BHI));
#pragma unroll
                for (int f = 0; f < 2; ++f) {
#pragma unroll
                    for (int jj = 0; jj < 2; ++jj) {
                        float* d = acc[f][2 * c + jj];
                        mma16816(d, ah[f], bh[2 * jj], bh[2 * jj + 1]);
                        mma16816(d, ah[f], bl[2 * jj], bl[2 * jj + 1]);
                        mma16816(d, al[f], bh[2 * jj], bh[2 * jj + 1]);
                    }
                }
            }
        }
    }

    // epilogue: bias + relu, direct global stores
#pragma unroll
    for (int f = 0; f < 2; ++f) {
#pragma unroll
        for (int j = 0; j < 8; ++j) {
            const int row = m0 + wm0 + f * 16 + (lane >> 2);
            const int col = n0 + wn0 + j * 8 + (lane & 3) * 2;
            const float b0 = __ldg(&bias[col]);
            const float b1 = __ldg(&bias[col + 1]);
            float2 v0, v1;
            v0.x = fmaxf(acc[f][j][0] + b0, 0.f);
            v0.y = fmaxf(acc[f][j][1] + b1, 0.f);
            v1.x = fmaxf(acc[f][j][2] + b0, 0.f);
            v1.y = fmaxf(acc[f][j][3] + b1, 0.f);
            *(float2*)(outp + (size_t)row * HDIM + col)       = v0;
            *(float2*)(outp + (size_t)(row + 8) * HDIM + col) = v1;
        }
    }
}

// ============================================================================
// Gates: one warp per batch row; computes FINAL gate weights (both softmaxes
// + sim mask applied here) so combine needs zero transcendentals.
// ============================================================================
__global__ __launch_bounds__(256)
void gates_kernel(const float* __restrict__ x,
                  const float* __restrict__ Wg,  const float* __restrict__ bg,
                  const float* __restrict__ Wgs, const float* __restrict__ bgs,
                  const int* __restrict__ sim)
{
    const int gwarp = (blockIdx.x * blockDim.x + threadIdx.x) >> 5;
    const int lane  = threadIdx.x & 31;
    if (gwarp >= BATCH) return;
    const int b = gwarp;

#pragma unroll
    for (int n = 0; n < 4; ++n) {
        const float* xr = x + ((size_t)n * BATCH + b) * DIN;
        float xv[16];
#pragma unroll
        for (int i = 0; i < 16; ++i) xv[i] = xr[lane + 32 * i];
        float zz[6];
#pragma unroll
        for (int e = 0; e < 6; ++e) {
            float acc = 0.f;
#pragma unroll
            for (int i = 0; i < 16; ++i)
                acc = fmaf(xv[i], Wg[(size_t)n * DIN * 6 + (size_t)(lane + 32 * i) * 6 + e], acc);
#pragma unroll
            for (int o = 16; o; o >>= 1) acc += __shfl_xor_sync(0xffffffffu, acc, o);
            zz[e] = acc + bg[n * 6 + e];   // all lanes hold full sum
        }
        // softmax 1
        float m1 = zz[0];
#pragma unroll
        for (int e = 1; e < 6; ++e) m1 = fmaxf(m1, zz[e]);
        float s1 = 0.f;
#pragma unroll
        for (int e = 0; e < 6; ++e) { zz[e] = __expf(zz[e] - m1); s1 += zz[e]; }
        const float inv1 = 1.f / s1;
#pragma unroll
        for (int e = 0; e < 6; ++e) zz[e] *= inv1;
        // mask + softmax 2
        const int s0 = sim[n * 2], s1i = sim[n * 2 + 1];
        bool valid[6];
        valid[0] = true; valid[1] = true;
#pragma unroll
        for (int e = 0; e < 4; ++e) valid[2 + e] = (s0 == e) || (s1i == e);
        float m2 = -1e30f;
#pragma unroll
        for (int e = 0; e < 6; ++e) if (valid[e]) m2 = fmaxf(m2, zz[e]);
        float w[6]; float s2 = 0.f;
#pragma unroll
        for (int e = 0; e < 6; ++e) { w[e] = valid[e] ? __expf(zz[e] - m2) : 0.f; s2 += w[e]; }
        const float inv2 = 1.f / s2;
        if (lane == 0) {
#pragma unroll
            for (int e = 0; e < 6; ++e)
                g_gw[((size_t)n * BATCH + b) * 6 + e] = w[e] * inv2;
        }
    }
    {
        const float* xr = x + ((size_t)4 * BATCH + b) * DIN;
        float xv[16];
#pragma unroll
        for (int i = 0; i < 16; ++i) xv[i] = xr[lane + 32 * i];
        float gs[12];
#pragma unroll
        for (int e = 0; e < 12; ++e) {
            float acc = 0.f;
#pragma unroll
            for (int i = 0; i < 16; ++i)
                acc = fmaf(xv[i], Wgs[(size_t)(lane + 32 * i) * 12 + e], acc);
#pragma unroll
            for (int o = 16; o; o >>= 1) acc += __shfl_xor_sync(0xffffffffu, acc, o);
            gs[e] = acc + bgs[e];
        }
        float m = gs[0];
#pragma unroll
        for (int e = 1; e < 12; ++e) m = fmaxf(m, gs[e]);
        float s = 0.f;
#pragma unroll
        for (int e = 0; e < 12; ++e) { gs[e] = __expf(gs[e] - m); s += gs[e]; }
        const float inv = 1.f / s;
        if (lane == 0) {
#pragma unroll
            for (int e = 0; e < 12; ++e)
                g_gsw[(size_t)b * 12 + e] = gs[e] * inv;
        }
    }
}

// ============================================================================
// Combine: pure weighted sums with precomputed weights (no exp).
// ============================================================================
__global__ __launch_bounds__(256)
void combine_kernel(float* __restrict__ out)
{
    __shared__ float w[36];   // [0..23] domain weights (4x6), [24..35] shared gs
    const int b = blockIdx.x;
    const int h = threadIdx.x;
    if (h < 24)       w[h] = g_gw[((size_t)(h / 6) * BATCH + b) * 6 + (h % 6)];
    else if (h < 36)  w[h] = g_gsw[(size_t)b * 12 + (h - 24)];
    __syncthreads();

    float sp[8];
#pragma unroll
    for (int j = 0; j < 8; ++j)
        sp[j] = g_spec[((size_t)j * BATCH + b) * HDIM + h];
    float sh[4];
#pragma unroll
    for (int e = 0; e < 4; ++e)
        sh[e] = g_shared[((size_t)e * BATCH + b) * HDIM + h];

    // shared-gate output
    float osh = 0.f;
#pragma unroll
    for (int j = 0; j < 8; ++j)  osh = fmaf(w[24 + j], sp[j], osh);
#pragma unroll
    for (int e = 0; e < 4; ++e)  osh = fmaf(w[32 + e], sh[e], osh);
    out[((size_t)4 * BATCH + b) * HDIM + h] = osh;

    // per-domain outputs
#pragma unroll
    for (int n = 0; n < 4; ++n) {
        float v = w[n * 6 + 0] * sp[2 * n] + w[n * 6 + 1] * sp[2 * n + 1];
        v = fmaf(w[n * 6 + 2], sh[0], v);
        v = fmaf(w[n * 6 + 3], sh[1], v);
        v = fmaf(w[n * 6 + 4], sh[2], v);
        v = fmaf(w[n * 6 + 5], sh[3], v);
        out[((size_t)n * BATCH + b) * HDIM + h] = v;
    }
}

// ============================================================================
extern "C" void kernel_launch(void* const* d_in, const int* in_sizes, int n_in,
                              void* d_out, int out_size)
{
    const float* x     = (const float*)d_in[0];
    const int*   sim   = (const int*)d_in[1];
    const float* Wspec = (const float*)d_in[2];
    const float* bspec = (const float*)d_in[3];
    const float* Wsh   = (const float*)d_in[4];
    const float* bsh   = (const float*)d_in[5];
    const float* Wg    = (const float*)d_in[6];
    const float* bg    = (const float*)d_in[7];
    const float* Wgs   = (const float*)d_in[8];
    const float* bgs   = (const float*)d_in[9];
    float* out = (float*)d_out;

    split_kernel<<<NSPLIT_BLOCKS, 256>>>((const float4*)x, (const float4*)Wspec,
                                         (const float4*)Wsh);

    cudaFuncSetAttribute(gemm_tc, cudaFuncAttributeMaxDynamicSharedMemorySize, GEMM_SMEM);
    dim3 gemm_grid(2, 128, 12);
    gemm_tc<<<gemm_grid, 256, GEMM_SMEM>>>(bspec, bsh);

    gates_kernel<<<BATCH / 8, 256>>>(x, Wg, bg, Wgs, bgs, sim);

    combine_kernel<<<BATCH, 256>>>(out);
}